// round 7
// baseline (speedup 1.0000x reference)
#include <cuda_runtime.h>
#include <cuda_bf16.h>
#include <math.h>

// DifferentiableCBFLayer: batched tiny QP (5 vars, 25 rows) via dual FISTA.
// TWO lanes per QP (even/odd) to double warp-level parallelism:
//   lane0: 10 obs rows + slack0 + boxA(2)   [all rows using x2]
//   lane1: 7 nei rows + conn + slack1/2 + boxW(2) [rows using x3/x4]
// Each lane holds 7 packed f32x2 row slots in uniform general-row form
// (G0*x0 + G1*x1 + GS*xsel + nB). Only S0,S1 cross lanes (2 shfl.xor/iter);
// S2 lives entirely in lane0, S3/S4 entirely in lane1. No divergence in the
// hot loop; lane differences are pure data (SEL on xa/xb + lane masks).

#define NOBS 10
#define NNEI 7
#define N_POWER 30
#define N_FISTA 300
#define PS 0.005f         // 1/(2*W_SLACK)
#define BIGV 1000.0f

typedef unsigned long long u64;

__device__ __forceinline__ u64 pk(float lo, float hi) {
    u64 r; asm("mov.b64 %0,{%1,%2};" : "=l"(r) : "f"(lo), "f"(hi)); return r;
}
__device__ __forceinline__ float lo_(u64 a) {
    float x; asm("{.reg .b32 h; mov.b64 {%0,h},%1;}" : "=f"(x) : "l"(a)); return x;
}
__device__ __forceinline__ float hi_(u64 a) {
    float x; asm("{.reg .b32 l; mov.b64 {l,%0},%1;}" : "=f"(x) : "l"(a)); return x;
}
__device__ __forceinline__ u64 fma2(u64 a, u64 b, u64 c) {
    u64 d; asm("fma.rn.f32x2 %0,%1,%2,%3;" : "=l"(d) : "l"(a), "l"(b), "l"(c)); return d;
}
__device__ __forceinline__ u64 mul2(u64 a, u64 b) {
    u64 d; asm("mul.rn.f32x2 %0,%1,%2;" : "=l"(d) : "l"(a), "l"(b)); return d;
}
__device__ __forceinline__ u64 relu2(u64 a) {
    u64 d;
    asm("{.reg .b32 l,h; mov.b64 {l,h},%1; max.f32 l,l,0f00000000; "
        "max.f32 h,h,0f00000000; mov.b64 %0,{l,h};}" : "=l"(d) : "l"(a));
    return d;
}
__device__ __forceinline__ float hadd(u64 a) { return lo_(a) + hi_(a); }
__device__ __forceinline__ float shx(float x) {
    return __shfl_xor_sync(0xffffffffu, x, 1);
}

// Partial sums of A^T * VEC over this lane's 7 slots.
// ga covers slots 0-2, gb covers slots 3-6 (their GS columns differ by lane).
#define PARTIALS(VEC, PS0, PS1, E, F, G)                                       \
  do {                                                                         \
    u64 a0 = mul2(G0p[0], (VEC)[0]);                                           \
    u64 a1 = mul2(G1p[0], (VEC)[0]);                                           \
    u64 ga = mul2(GSp[0], (VEC)[0]);                                           \
    _Pragma("unroll")                                                          \
    for (int j = 1; j < 3; j++) {                                              \
      a0 = fma2(G0p[j], (VEC)[j], a0);                                         \
      a1 = fma2(G1p[j], (VEC)[j], a1);                                         \
      ga = fma2(GSp[j], (VEC)[j], ga);                                         \
    }                                                                          \
    u64 gb = mul2(GSp[3], (VEC)[3]);                                           \
    a0 = fma2(G0p[3], (VEC)[3], a0);                                           \
    a1 = fma2(G1p[3], (VEC)[3], a1);                                           \
    _Pragma("unroll")                                                          \
    for (int j = 4; j < 7; j++) {                                              \
      a0 = fma2(G0p[j], (VEC)[j], a0);                                         \
      a1 = fma2(G1p[j], (VEC)[j], a1);                                         \
      gb = fma2(GSp[j], (VEC)[j], gb);                                         \
    }                                                                          \
    PS0 = hadd(a0); PS1 = hadd(a1);                                            \
    E = hadd(ga); F = lo_(gb); G = hi_(gb);                                    \
  } while (0)

__global__ __launch_bounds__(32)
void cbf_fista_kernel(const float* __restrict__ u_nom,
                      const float* __restrict__ v_cur,
                      const float* __restrict__ p_obs,
                      const float* __restrict__ obs_mask,
                      const float* __restrict__ p_ag,
                      const float* __restrict__ v_ag,
                      const float* __restrict__ ag_mask,
                      const float* __restrict__ p_c,
                      const float* __restrict__ v_c,
                      const float* __restrict__ c_mask,
                      float* __restrict__ out, int B)
{
    int t = blockIdx.x * 32 + threadIdx.x;
    int q = t >> 1;
    if (q >= B) return;
    const int par = t & 1;

    const float2 u  = ((const float2*)u_nom)[q];
    const float u0 = u.x, u1 = u.y;
    const float v  = v_cur[q];

    u64 G0p[7], G1p[7], GSp[7], nBp[7];

    if (par == 0) {
        // ---- lane0: 5 obs pairs, (slack0,dummy), boxA ----
        #pragma unroll
        for (int jj = 0; jj < 5; jj++) {
            float g0[2], g1[2], gs[2], nb[2];
            #pragma unroll
            for (int s = 0; s < 2; s++) {
                int i = 2 * jj + s;
                float2 p = ((const float2*)p_obs)[q * NOBS + i];
                float m  = obs_mask[q * NOBS + i];
                g0[s] = 2.f * p.x * m;
                g1[s] = 2.f * p.y * v * m;
                gs[s] = -m;
                float h   = p.x * p.x + p.y * p.y - 0.25f;
                float hd  = -2.f * p.x * v;
                float rhs = 2.f * v * v + 3.f * hd + 2.f * h;
                nb[s] = -((m > 0.f) ? rhs : BIGV);
            }
            G0p[jj] = pk(g0[0], g0[1]); G1p[jj] = pk(g1[0], g1[1]);
            GSp[jj] = pk(gs[0], gs[1]); nBp[jj] = pk(nb[0], nb[1]);
        }
        G0p[5] = 0;               G1p[5] = 0;
        GSp[5] = pk(-1.f, 0.f);   nBp[5] = 0;                  // slack0 + dummy
        G0p[6] = pk(-1.f, 1.f);   G1p[6] = 0;
        GSp[6] = 0;               nBp[6] = pk(-2.f, -2.f);     // boxA (+-a<=2)
    } else {
        // ---- lane1: 3 nei pairs, (nei6,conn), (slack1,slack2), boxW, dummy ----
        #pragma unroll
        for (int jj = 0; jj < 3; jj++) {
            float g0[2], g1[2], gs[2], nb[2];
            #pragma unroll
            for (int s = 0; s < 2; s++) {
                int i = 2 * jj + s;
                float2 pa = ((const float2*)p_ag)[q * NNEI + i];
                float2 va = ((const float2*)v_ag)[q * NNEI + i];
                float m   = ag_mask[q * NNEI + i];
                float ax = pa.x, ay = pa.y, vjx = va.x, vjy = va.y;
                g0[s] = 2.f * ax * m;
                g1[s] = (2.f * ay * v - 2.f * ay * vjx + 2.f * ax * vjy) * m;
                gs[s] = -m;
                float h   = ax * ax + ay * ay - 0.64f;
                float hd  = -2.f * ax * v + 2.f * (ax * vjx + ay * vjy);
                float hdd = 2.f * v * v - 4.f * v * vjx + 2.f * vjx * vjx + 2.f * vjy * vjy;
                float rhs = hdd + 3.f * hd + 2.f * h;
                nb[s] = -((m > 0.f) ? rhs : BIGV);
            }
            G0p[jj] = pk(g0[0], g0[1]); G1p[jj] = pk(g1[0], g1[1]);
            GSp[jj] = pk(gs[0], gs[1]); nBp[jj] = pk(nb[0], nb[1]);
        }
        {
            // lo: nei row 6
            float2 pa = ((const float2*)p_ag)[q * NNEI + 6];
            float2 va = ((const float2*)v_ag)[q * NNEI + 6];
            float m   = ag_mask[q * NNEI + 6];
            float ax = pa.x, ay = pa.y, vjx = va.x, vjy = va.y;
            float g0l = 2.f * ax * m;
            float g1l = (2.f * ay * v - 2.f * ay * vjx + 2.f * ax * vjy) * m;
            float gsl = -m;
            float h   = ax * ax + ay * ay - 0.64f;
            float hd  = -2.f * ax * v + 2.f * (ax * vjx + ay * vjy);
            float hdd = 2.f * v * v - 4.f * v * vjx + 2.f * vjx * vjx + 2.f * vjy * vjy;
            float nbl = -((m > 0.f) ? (hdd + 3.f * hd + 2.f * h) : BIGV);
            // hi: connectivity row
            float2 pc = ((const float2*)p_c)[q];
            float2 vc = ((const float2*)v_c)[q];
            float mc  = c_mask[q];
            float cx = pc.x, cy = pc.y, cvx = vc.x, cvy = vc.y;
            float g0h = -2.f * cx * mc;
            float g1h = -(2.f * cy * v - 2.f * cy * cvx + 2.f * cx * cvy) * mc;
            float gsh = -mc;
            float hc   = 25.f - (cx * cx + cy * cy);
            float hdc  = 2.f * cx * v - 2.f * (cx * cvx + cy * cvy);
            float hddc = -(2.f * v * v - 4.f * v * cvx + 2.f * cvx * cvx + 2.f * cvy * cvy);
            float nbh = -((mc > 0.f) ? (hddc + 3.f * hdc + 2.f * hc) : BIGV);
            G0p[3] = pk(g0l, g0h); G1p[3] = pk(g1l, g1h);
            GSp[3] = pk(gsl, gsh); nBp[3] = pk(nbl, nbh);
        }
        G0p[4] = 0;               G1p[4] = 0;
        GSp[4] = pk(-1.f, -1.f);  nBp[4] = 0;                  // slack1, slack2
        G0p[5] = 0;               G1p[5] = pk(-1.f, 1.f);
        GSp[5] = 0;               nBp[5] = pk(-1.f, -1.f);     // boxW (+-w<=1)
        G0p[6] = 0; G1p[6] = 0; GSp[6] = 0; nBp[6] = 0;        // dummy
    }

    // ---- power iteration for L = lambda_max(A Pinv A^T) ----
    u64 vp[7];
    #pragma unroll
    for (int j = 0; j < 7; j++) vp[j] = pk(1.f, 1.f);

    float L;
    {
        float pS0, pS1, e, f, g;
        #pragma unroll 1
        for (int it = 0; it < N_POWER; ++it) {
            PARTIALS(vp, pS0, pS1, e, f, g);
            float h  = e + f;
            float S0 = pS0 + shx(pS0);
            float S1 = pS1 + shx(pS1);
            float hg = h + g;
            float Sa = par ? h : hg;
            float Sb = par ? g : hg;
            float t0 = 0.5f * S0, t1 = 0.5f * S1;
            float ta = PS * Sa,   tb = PS * Sb;
            u64 T0P = pk(t0, t0), T1P = pk(t1, t1);
            u64 XA  = pk(ta, ta), XB  = pk(ta, tb);
            u64 w[7];
            #pragma unroll
            for (int j = 0; j < 3; j++)
                w[j] = fma2(G0p[j], T0P, fma2(G1p[j], T1P, mul2(GSp[j], XA)));
            #pragma unroll
            for (int j = 3; j < 7; j++)
                w[j] = fma2(G0p[j], T0P, fma2(G1p[j], T1P, mul2(GSp[j], XB)));
            u64 n2p = mul2(w[0], w[0]);
            #pragma unroll
            for (int j = 1; j < 7; j++) n2p = fma2(w[j], w[j], n2p);
            float n2 = hadd(n2p);
            n2 += shx(n2);
            float inv = 1.f / (sqrtf(n2) + 1e-12f);
            u64 IV = pk(inv, inv);
            #pragma unroll
            for (int j = 0; j < 7; j++) vp[j] = mul2(w[j], IV);
        }
        // L = v . M v
        PARTIALS(vp, pS0, pS1, e, f, g);
        float h  = e + f;
        float S0 = pS0 + shx(pS0);
        float S1 = pS1 + shx(pS1);
        float hg = h + g;
        float Sa = par ? h : hg;
        float Sb = par ? g : hg;
        float t0 = 0.5f * S0, t1 = 0.5f * S1;
        float ta = PS * Sa,   tb = PS * Sb;
        u64 T0P = pk(t0, t0), T1P = pk(t1, t1);
        u64 XA  = pk(ta, ta), XB  = pk(ta, tb);
        u64 dp;
        {
            u64 w0 = fma2(G0p[0], T0P, fma2(G1p[0], T1P, mul2(GSp[0], XA)));
            dp = mul2(vp[0], w0);
        }
        #pragma unroll
        for (int j = 1; j < 3; j++) {
            u64 wj = fma2(G0p[j], T0P, fma2(G1p[j], T1P, mul2(GSp[j], XA)));
            dp = fma2(vp[j], wj, dp);
        }
        #pragma unroll
        for (int j = 3; j < 7; j++) {
            u64 wj = fma2(G0p[j], T0P, fma2(G1p[j], T1P, mul2(GSp[j], XB)));
            dp = fma2(vp[j], wj, dp);
        }
        float d = hadd(dp);
        L = d + shx(d);
    }
    const float step = 1.f / (L + 1e-6f);
    const u64 STEPP = pk(step, step);

    // ---- FISTA on the dual ----
    u64 ln[7], lno[7];
    #pragma unroll
    for (int j = 0; j < 7; j++) { ln[j] = 0ull; lno[j] = 0ull; }
    float SL0n = 0.f, SL0o = 0.f, SL1n = 0.f, SL1o = 0.f;
    float SLan = 0.f, SLao = 0.f, SLbn = 0.f, SLbo = 0.f;
    float tk = 1.f, b1 = 1.f, bn = 0.f;   // beta_0 = 0

    #pragma unroll 2
    for (int it = 0; it < N_FISTA; ++it) {
        // x = x_of(y_k), y reconstructed with previous iteration's beta
        float m0 = -0.5f * b1, m0o = -0.5f * bn;
        float pa = -PS * b1,   pao = -PS * bn;
        float x0 = fmaf(m0, SL0n, fmaf(m0o, SL0o, u0));
        float x1 = fmaf(m0, SL1n, fmaf(m0o, SL1o, u1));
        float xa = fmaf(pa, SLan, pao * SLao);
        float xb = fmaf(pa, SLbn, pao * SLbo);

        u64 B1P = pk(b1, b1), BNP = pk(bn, bn);
        u64 X0P = pk(x0, x0), X1P = pk(x1, x1);
        u64 XA  = pk(xa, xa), XB  = pk(xa, xb);

        u64 a0, a1, ga, gb;
        {
            u64 y  = fma2(B1P, ln[0], mul2(BNP, lno[0]));
            u64 r  = fma2(G0p[0], X0P, fma2(G1p[0], X1P, fma2(GSp[0], XA, nBp[0])));
            u64 nl = relu2(fma2(STEPP, r, y));
            lno[0] = ln[0]; ln[0] = nl;
            a0 = mul2(G0p[0], nl); a1 = mul2(G1p[0], nl); ga = mul2(GSp[0], nl);
        }
        #pragma unroll
        for (int j = 1; j < 3; j++) {
            u64 y  = fma2(B1P, ln[j], mul2(BNP, lno[j]));
            u64 r  = fma2(G0p[j], X0P, fma2(G1p[j], X1P, fma2(GSp[j], XA, nBp[j])));
            u64 nl = relu2(fma2(STEPP, r, y));
            lno[j] = ln[j]; ln[j] = nl;
            a0 = fma2(G0p[j], nl, a0); a1 = fma2(G1p[j], nl, a1);
            ga = fma2(GSp[j], nl, ga);
        }
        {
            u64 y  = fma2(B1P, ln[3], mul2(BNP, lno[3]));
            u64 r  = fma2(G0p[3], X0P, fma2(G1p[3], X1P, fma2(GSp[3], XB, nBp[3])));
            u64 nl = relu2(fma2(STEPP, r, y));
            lno[3] = ln[3]; ln[3] = nl;
            a0 = fma2(G0p[3], nl, a0); a1 = fma2(G1p[3], nl, a1);
            gb = mul2(GSp[3], nl);
        }
        #pragma unroll
        for (int j = 4; j < 7; j++) {
            u64 y  = fma2(B1P, ln[j], mul2(BNP, lno[j]));
            u64 r  = fma2(G0p[j], X0P, fma2(G1p[j], X1P, fma2(GSp[j], XB, nBp[j])));
            u64 nl = relu2(fma2(STEPP, r, y));
            lno[j] = ln[j]; ln[j] = nl;
            a0 = fma2(G0p[j], nl, a0); a1 = fma2(G1p[j], nl, a1);
            gb = fma2(GSp[j], nl, gb);
        }

        float pS0 = hadd(a0), pS1 = hadd(a1);
        float e = hadd(ga), f = lo_(gb), g = hi_(gb);
        float h  = e + f;
        float hg = h + g;
        float S0 = pS0 + shx(pS0);
        float S1 = pS1 + shx(pS1);
        float SLa_new = par ? h : hg;
        float SLb_new = par ? g : hg;

        // beta for the next iteration
        float tk1  = 0.5f * (1.f + sqrtf(fmaf(4.f * tk, tk, 1.f)));
        float beta = __fdividef(tk - 1.f, tk1);
        tk = tk1;
        b1 = 1.f + beta; bn = -beta;

        SL0o = SL0n; SL0n = S0;
        SL1o = SL1n; SL1n = S1;
        SLao = SLan; SLan = SLa_new;
        SLbo = SLbn; SLbn = SLb_new;
    }

    if (par == 0) {
        float x0 = fmaf(-0.5f, SL0n, u0);
        float x1 = fmaf(-0.5f, SL1n, u1);
        ((float2*)out)[q] = make_float2(x0, x1);
    }
}

extern "C" void kernel_launch(void* const* d_in, const int* in_sizes, int n_in,
                              void* d_out, int out_size) {
    const float* u_nom   = (const float*)d_in[0];
    const float* v_cur   = (const float*)d_in[1];
    const float* p_obs   = (const float*)d_in[2];
    const float* obs_m   = (const float*)d_in[3];
    const float* p_ag    = (const float*)d_in[4];
    const float* v_ag    = (const float*)d_in[5];
    const float* ag_m    = (const float*)d_in[6];
    const float* p_c     = (const float*)d_in[7];
    const float* v_c     = (const float*)d_in[8];
    const float* c_m     = (const float*)d_in[9];
    float* out = (float*)d_out;

    int B = in_sizes[0] / 2;
    long long total = 2LL * B;
    int threads = 32;
    int blocks  = (int)((total + threads - 1) / threads);
    cbf_fista_kernel<<<blocks, threads>>>(u_nom, v_cur, p_obs, obs_m, p_ag, v_ag,
                                          ag_m, p_c, v_c, c_m, out, B);
}